// round 1
// baseline (speedup 1.0000x reference)
#include <cuda_runtime.h>
#include <cuda_bf16.h>
#include <math.h>

// Problem constants
#define Bv 2
#define Sv 2048
#define Dv 1024
#define Hv 16
#define DKv 64
#define MSZ (Bv * Sv)          // 4096 rows for all projections

// ---------------- scratch (static device arrays: allocation-guard safe) ----
__device__ float g_Q[MSZ * Dv];     // 16 MB, layout [b*S+s][D] (head h at col h*64)
__device__ float g_K[MSZ * Dv];
__device__ float g_V[MSZ * Dv];
__device__ float g_Ctx[MSZ * Dv];   // attention output, [b*S+s][D]

// ---------------- GEMM: C[M,N] = A[M,K] * B[N,K]^T  (all row-major) -------
#define BM 128
#define BN 128
#define BK 8
#define TM 8
#define TN 8
// block = 256 threads (16x16), grid = (N/BN, M/BM). M,N,K multiples of tile.
__global__ __launch_bounds__(256) void gemm_tn(const float* __restrict__ A,
                                               const float* __restrict__ B,
                                               float* __restrict__ C,
                                               int M, int N, int K) {
    __shared__ float As[BK][BM];
    __shared__ float Bs[BK][BN];

    const int tid = threadIdx.x;
    const int tx = tid % 16;
    const int ty = tid / 16;
    const int row0 = blockIdx.y * BM;
    const int col0 = blockIdx.x * BN;

    // staging: each thread loads one float4 of A-tile and one of B-tile
    const int lrow = tid >> 1;            // 0..127
    const int lcol = (tid & 1) * 4;       // 0 or 4

    float acc[TM][TN];
#pragma unroll
    for (int i = 0; i < TM; ++i)
#pragma unroll
        for (int j = 0; j < TN; ++j) acc[i][j] = 0.f;

    for (int k0 = 0; k0 < K; k0 += BK) {
        float4 a4 = *(const float4*)&A[(size_t)(row0 + lrow) * K + k0 + lcol];
        float4 b4 = *(const float4*)&B[(size_t)(col0 + lrow) * K + k0 + lcol];
        __syncthreads();   // protect previous-iter reads before overwrite
        As[lcol + 0][lrow] = a4.x; As[lcol + 1][lrow] = a4.y;
        As[lcol + 2][lrow] = a4.z; As[lcol + 3][lrow] = a4.w;
        Bs[lcol + 0][lrow] = b4.x; Bs[lcol + 1][lrow] = b4.y;
        Bs[lcol + 2][lrow] = b4.z; Bs[lcol + 3][lrow] = b4.w;
        __syncthreads();

#pragma unroll
        for (int k = 0; k < BK; ++k) {
            float ar[TM], br[TN];
            float4 t;
            t = *(const float4*)&As[k][ty * TM + 0]; ar[0]=t.x; ar[1]=t.y; ar[2]=t.z; ar[3]=t.w;
            t = *(const float4*)&As[k][ty * TM + 4]; ar[4]=t.x; ar[5]=t.y; ar[6]=t.z; ar[7]=t.w;
            t = *(const float4*)&Bs[k][tx * TN + 0]; br[0]=t.x; br[1]=t.y; br[2]=t.z; br[3]=t.w;
            t = *(const float4*)&Bs[k][tx * TN + 4]; br[4]=t.x; br[5]=t.y; br[6]=t.z; br[7]=t.w;
#pragma unroll
            for (int i = 0; i < TM; ++i)
#pragma unroll
                for (int j = 0; j < TN; ++j)
                    acc[i][j] = fmaf(ar[i], br[j], acc[i][j]);
        }
    }

#pragma unroll
    for (int i = 0; i < TM; ++i) {
        float* cp = &C[(size_t)(row0 + ty * TM + i) * N + col0 + tx * TN];
        float4 o0 = make_float4(acc[i][0], acc[i][1], acc[i][2], acc[i][3]);
        float4 o1 = make_float4(acc[i][4], acc[i][5], acc[i][6], acc[i][7]);
        *(float4*)(cp + 0) = o0;
        *(float4*)(cp + 4) = o1;
    }
}

// ---------------- flash attention (causal), fp32 --------------------------
// grid: (S/AM, B*H), block: AM threads. Each thread owns one query row.
#define AM 128
#define AN 32
__global__ __launch_bounds__(AM) void flash_attn(const float* __restrict__ Q,
                                                 const float* __restrict__ K,
                                                 const float* __restrict__ V,
                                                 float* __restrict__ O) {
    const int bh = blockIdx.y;
    const int b = bh / Hv;
    const int h = bh % Hv;
    const int qt = blockIdx.x;
    const int tid = threadIdx.x;
    const int qrow = qt * AM + tid;              // global query index within sequence

    const float* qptr = Q + ((size_t)(b * Sv + qrow)) * Dv + h * DKv;
    float qv[DKv];
#pragma unroll
    for (int d = 0; d < DKv; d += 4) {
        float4 t = *(const float4*)(qptr + d);
        qv[d] = t.x; qv[d + 1] = t.y; qv[d + 2] = t.z; qv[d + 3] = t.w;
    }

    float o[DKv];
#pragma unroll
    for (int d = 0; d < DKv; ++d) o[d] = 0.f;
    float mmax = -1e30f, lsum = 0.f;

    __shared__ float Ks[AN][DKv];
    __shared__ float Vs[AN][DKv];

    const int kend = (qt + 1) * AM;              // keys needed: < kend (causal)
    for (int k0 = 0; k0 < kend; k0 += AN) {
        __syncthreads();                          // protect previous-iter reads
        // stage K/V tile: 32x64 floats each, 128 threads x 4 float4
#pragma unroll
        for (int t = 0; t < 4; ++t) {
            int i4 = tid + t * AM;                // 0..511
            int j = i4 >> 4;                      // row 0..31
            int c = (i4 & 15) * 4;                // col 0..60
            size_t base = ((size_t)(b * Sv + k0 + j)) * Dv + h * DKv + c;
            *(float4*)&Ks[j][c] = *(const float4*)(K + base);
            *(float4*)&Vs[j][c] = *(const float4*)(V + base);
        }
        __syncthreads();

        float s[AN];
#pragma unroll
        for (int j = 0; j < AN; ++j) {
            float a = 0.f;
#pragma unroll
            for (int d = 0; d < DKv; d += 4) {
                float4 kk = *(const float4*)&Ks[j][d];
                a = fmaf(qv[d], kk.x, a);
                a = fmaf(qv[d + 1], kk.y, a);
                a = fmaf(qv[d + 2], kk.z, a);
                a = fmaf(qv[d + 3], kk.w, a);
            }
            s[j] = (k0 + j <= qrow) ? a * 0.125f : -1e30f;  // 1/sqrt(64)
        }

        float tmax = s[0];
#pragma unroll
        for (int j = 1; j < AN; ++j) tmax = fmaxf(tmax, s[j]);
        float mnew = fmaxf(mmax, tmax);
        float alpha = __expf(mmax - mnew);
        lsum *= alpha;
#pragma unroll
        for (int d = 0; d < DKv; ++d) o[d] *= alpha;

#pragma unroll
        for (int j = 0; j < AN; ++j) {
            float p = __expf(s[j] - mnew);
            lsum += p;
#pragma unroll
            for (int d = 0; d < DKv; d += 4) {
                float4 vv = *(const float4*)&Vs[j][d];
                o[d]     = fmaf(p, vv.x, o[d]);
                o[d + 1] = fmaf(p, vv.y, o[d + 1]);
                o[d + 2] = fmaf(p, vv.z, o[d + 2]);
                o[d + 3] = fmaf(p, vv.w, o[d + 3]);
            }
        }
        mmax = mnew;
    }

    float inv = 1.f / lsum;
    float* optr = O + ((size_t)(b * Sv + qrow)) * Dv + h * DKv;
#pragma unroll
    for (int d = 0; d < DKv; d += 4) {
        float4 t = make_float4(o[d] * inv, o[d + 1] * inv, o[d + 2] * inv, o[d + 3] * inv);
        *(float4*)(optr + d) = t;
    }
}

// ---------------- launch ---------------------------------------------------
extern "C" void kernel_launch(void* const* d_in, const int* in_sizes, int n_in,
                              void* d_out, int out_size) {
    // inputs: q, k, v, mask, Wq, Wk, Wv, Wo
    const float* q  = (const float*)d_in[0];
    const float* k  = (const float*)d_in[1];
    const float* v  = (const float*)d_in[2];
    // d_in[3] = mask (tril) — handled analytically
    const float* Wq = (const float*)d_in[4];
    const float* Wk = (const float*)d_in[5];
    const float* Wv = (const float*)d_in[6];
    const float* Wo = (const float*)d_in[7];
    float* out = (float*)d_out;

    float *gq, *gk, *gv, *gc;
    cudaGetSymbolAddress((void**)&gq, g_Q);
    cudaGetSymbolAddress((void**)&gk, g_K);
    cudaGetSymbolAddress((void**)&gv, g_V);
    cudaGetSymbolAddress((void**)&gc, g_Ctx);

    dim3 gblock(256);
    dim3 ggrid(Dv / BN, MSZ / BM);   // (8, 32)

    gemm_tn<<<ggrid, gblock>>>(q, Wq, gq, MSZ, Dv, Dv);
    gemm_tn<<<ggrid, gblock>>>(k, Wk, gk, MSZ, Dv, Dv);
    gemm_tn<<<ggrid, gblock>>>(v, Wv, gv, MSZ, Dv, Dv);

    dim3 ablock(AM);
    dim3 agrid(Sv / AM, Bv * Hv);    // (16, 32)
    flash_attn<<<agrid, ablock>>>(gq, gk, gv, gc);

    gemm_tn<<<ggrid, gblock>>>(gc, Wo, out, MSZ, Dv, Dv);
}

// round 3
// speedup vs baseline: 1.1374x; 1.1374x over previous
#include <cuda_runtime.h>
#include <cuda_bf16.h>
#include <math.h>
#include <stdint.h>

#define Bv 2
#define Sv 2048
#define Dv 1024
#define Hv 16
#define DKv 64
#define MSZ (Bv * Sv)

// ---------------- scratch ---------------------------------------------------
__device__ float g_Q[MSZ * Dv];
__device__ float g_K[MSZ * Dv];
__device__ float g_V[MSZ * Dv];
__device__ float g_Ctx[MSZ * Dv];

// ---------------- bf16 hi/lo split -------------------------------------------
__device__ __forceinline__ void split4(float4 v, uint2& h, uint2& l) {
    __nv_bfloat162 h01 = __float22bfloat162_rn(make_float2(v.x, v.y));
    __nv_bfloat162 h23 = __float22bfloat162_rn(make_float2(v.z, v.w));
    float2 f01 = __bfloat1622float2(h01);
    float2 f23 = __bfloat1622float2(h23);
    __nv_bfloat162 l01 = __float22bfloat162_rn(make_float2(v.x - f01.x, v.y - f01.y));
    __nv_bfloat162 l23 = __float22bfloat162_rn(make_float2(v.z - f23.x, v.w - f23.y));
    h.x = *(uint32_t*)&h01; h.y = *(uint32_t*)&h23;
    l.x = *(uint32_t*)&l01; l.y = *(uint32_t*)&l23;
}

// ---------------- warp mma (sm_80+ path, compiles for plain sm_103) ----------
__device__ __forceinline__ void mma_bf16(float* d, const uint32_t* a, const uint32_t* b) {
    asm volatile(
        "mma.sync.aligned.m16n8k16.row.col.f32.bf16.bf16.f32 "
        "{%0,%1,%2,%3}, {%4,%5,%6,%7}, {%8,%9}, {%0,%1,%2,%3};"
        : "+f"(d[0]), "+f"(d[1]), "+f"(d[2]), "+f"(d[3])
        : "r"(a[0]), "r"(a[1]), "r"(a[2]), "r"(a[3]), "r"(b[0]), "r"(b[1]));
}

// ---------------- tensor-core GEMM: C[M,N] = A[M,K] * B[N,K]^T ----------------
// CTA 128x128, 8 warps (2m x 4n), warp tile 64x32 = 4x4 m16n8 frags.
// K chunks of 32, double-buffered smem, 3xbf16 split (hi*hi + hi*lo + lo*hi).
#define KC 32
#define NCH (Dv / KC)          // 32
#define ROWB 80                // bytes per smem row: 64B data + 16B pad (conflict-free)
#define TILEB (128 * ROWB)     // 10240 per tile
#define STAGEB (4 * TILEB)     // Ahi/Alo/Bhi/Blo = 40960
#define GEMM_SMEM (2 * STAGEB) // 81920

__global__ __launch_bounds__(256, 1)
void gemm_tc(const float* __restrict__ A, const float* __restrict__ B,
             float* __restrict__ C) {
    extern __shared__ char smem[];
    const int tid = threadIdx.x;
    const int wid = tid >> 5;
    const int lid = tid & 31;
    const int g = lid >> 2;        // group 0..7
    const int tig = lid & 3;       // thread-in-group 0..3
    const int warp_m = wid & 1;    // 0..1  (64 rows each)
    const int warp_n = wid >> 1;   // 0..3  (32 cols each)
    const int row0 = blockIdx.y * 128;
    const int col0 = blockIdx.x * 128;

    float acc[4][4][4];
#pragma unroll
    for (int i = 0; i < 4; ++i)
#pragma unroll
        for (int j = 0; j < 4; ++j)
#pragma unroll
            for (int e = 0; e < 4; ++e) acc[i][j][e] = 0.f;

    float4 ra[4], rb[4];

    // ---- load chunk into regs ----
    auto load_chunk = [&](int k0) {
#pragma unroll
        for (int t = 0; t < 4; ++t) {
            int idx = tid + t * 256;       // 0..1023
            int r = idx >> 3;              // 0..127
            int c = (idx & 7) * 4;         // 0..28
            ra[t] = *(const float4*)&A[(size_t)(row0 + r) * Dv + k0 + c];
            rb[t] = *(const float4*)&B[(size_t)(col0 + r) * Dv + k0 + c];
        }
    };
    // ---- split + store regs into a stage ----
    auto store_chunk = [&](int s) {
        char* st = smem + s * STAGEB;
#pragma unroll
        for (int t = 0; t < 4; ++t) {
            int idx = tid + t * 256;
            int r = idx >> 3;
            int c4 = idx & 7;
            uint32_t off = (uint32_t)(r * ROWB + c4 * 8);
            uint2 h, l;
            split4(ra[t], h, l);
            *(uint2*)(st + off) = h;                     // Ahi
            *(uint2*)(st + TILEB + off) = l;             // Alo
            split4(rb[t], h, l);
            *(uint2*)(st + 2 * TILEB + off) = h;         // Bhi
            *(uint2*)(st + 3 * TILEB + off) = l;         // Blo
        }
    };
    // ---- compute one stage (2 k16 steps) ----
    auto compute = [&](int s) {
        const char* st = smem + s * STAGEB;
#pragma unroll
        for (int ks = 0; ks < 2; ++ks) {
            const int kb = ks * 32;   // byte offset of k16 step within row
            uint32_t ah[4][4], al[4][4], bh[4][2], bl[4][2];
#pragma unroll
            for (int mt = 0; mt < 4; ++mt) {
                int r = warp_m * 64 + mt * 16 + g;
                const char* p = st + r * ROWB + tig * 4 + kb;
                ah[mt][0] = *(const uint32_t*)(p);
                ah[mt][1] = *(const uint32_t*)(p + 8 * ROWB);
                ah[mt][2] = *(const uint32_t*)(p + 16);
                ah[mt][3] = *(const uint32_t*)(p + 8 * ROWB + 16);
                al[mt][0] = *(const uint32_t*)(p + TILEB);
                al[mt][1] = *(const uint32_t*)(p + TILEB + 8 * ROWB);
                al[mt][2] = *(const uint32_t*)(p + TILEB + 16);
                al[mt][3] = *(const uint32_t*)(p + TILEB + 8 * ROWB + 16);
            }
#pragma unroll
            for (int nt = 0; nt < 4; ++nt) {
                int r = warp_n * 32 + nt * 8 + g;
                const char* p = st + 2 * TILEB + r * ROWB + tig * 4 + kb;
                bh[nt][0] = *(const uint32_t*)(p);
                bh[nt][1] = *(const uint32_t*)(p + 16);
                bl[nt][0] = *(const uint32_t*)(p + TILEB);
                bl[nt][1] = *(const uint32_t*)(p + TILEB + 16);
            }
#pragma unroll
            for (int mt = 0; mt < 4; ++mt)
#pragma unroll
                for (int nt = 0; nt < 4; ++nt) {
                    mma_bf16(acc[mt][nt], ah[mt], bh[nt]);
                    mma_bf16(acc[mt][nt], ah[mt], bl[nt]);
                    mma_bf16(acc[mt][nt], al[mt], bh[nt]);
                }
        }
    };

    load_chunk(0);
    store_chunk(0);
    __syncthreads();
    for (int i = 0; i < NCH; ++i) {
        if (i + 1 < NCH) load_chunk((i + 1) * KC);
        compute(i & 1);
        __syncthreads();
        if (i + 1 < NCH) {
            store_chunk((i + 1) & 1);
            __syncthreads();
        }
    }

    // epilogue
#pragma unroll
    for (int mt = 0; mt < 4; ++mt)
#pragma unroll
        for (int nt = 0; nt < 4; ++nt) {
            int r = row0 + warp_m * 64 + mt * 16 + g;
            int c = col0 + warp_n * 32 + nt * 8 + 2 * tig;
            float* d = acc[mt][nt];
            *(float2*)&C[(size_t)r * Dv + c] = make_float2(d[0], d[1]);
            *(float2*)&C[(size_t)(r + 8) * Dv + c] = make_float2(d[2], d[3]);
        }
}

// ---------------- flash attention (causal), fp32, DK split across pairs ------
#define AMQ 128
#define AN 32
__global__ __launch_bounds__(256, 2)
void flash_attn2(const float* __restrict__ Q, const float* __restrict__ K,
                 const float* __restrict__ V, float* __restrict__ O) {
    __shared__ float Ks[AN][DKv];
    __shared__ float Vs[AN][DKv];

    const int bh = blockIdx.y;
    const int b = bh >> 4;
    const int h = bh & 15;
    const int qt = blockIdx.x;
    const int tid = threadIdx.x;
    const int ql = tid >> 1;
    const int hf = tid & 1;
    const int qrow = qt * AMQ + ql;

    const float* qptr = Q + ((size_t)(b * Sv + qrow)) * Dv + h * DKv + hf * 32;
    float qv[32];
#pragma unroll
    for (int d = 0; d < 32; d += 4) {
        float4 t = *(const float4*)(qptr + d);
        qv[d] = t.x; qv[d + 1] = t.y; qv[d + 2] = t.z; qv[d + 3] = t.w;
    }

    float o[32];
#pragma unroll
    for (int d = 0; d < 32; ++d) o[d] = 0.f;
    float mmax = -1e30f, lsum = 0.f;

    const int kend = (qt + 1) * AMQ;
    for (int k0 = 0; k0 < kend; k0 += AN) {
        __syncthreads();
#pragma unroll
        for (int t = 0; t < 2; ++t) {
            int idx = tid + t * 256;
            int j = idx >> 4;
            int c = (idx & 15) * 4;
            size_t base = ((size_t)(b * Sv + k0 + j)) * Dv + h * DKv + c;
            *(float4*)&Ks[j][c] = *(const float4*)(K + base);
            *(float4*)&Vs[j][c] = *(const float4*)(V + base);
        }
        __syncthreads();

        float s[AN];
#pragma unroll
        for (int j = 0; j < AN; ++j) {
            float a = 0.f;
#pragma unroll
            for (int d = 0; d < 32; d += 4) {
                float4 kk = *(const float4*)&Ks[j][hf * 32 + d];
                a = fmaf(qv[d], kk.x, a);
                a = fmaf(qv[d + 1], kk.y, a);
                a = fmaf(qv[d + 2], kk.z, a);
                a = fmaf(qv[d + 3], kk.w, a);
            }
            a += __shfl_xor_sync(0xffffffffu, a, 1);
            s[j] = (k0 + j <= qrow) ? a * 0.125f : -1e30f;
        }

        float tmax = s[0];
#pragma unroll
        for (int j = 1; j < AN; ++j) tmax = fmaxf(tmax, s[j]);
        float mnew = fmaxf(mmax, tmax);
        float alpha = __expf(mmax - mnew);
        lsum *= alpha;
#pragma unroll
        for (int d = 0; d < 32; ++d) o[d] *= alpha;

#pragma unroll
        for (int j = 0; j < AN; ++j) {
            float p = __expf(s[j] - mnew);
            lsum += p;
#pragma unroll
            for (int d = 0; d < 32; d += 4) {
                float4 vv = *(const float4*)&Vs[j][hf * 32 + d];
                o[d]     = fmaf(p, vv.x, o[d]);
                o[d + 1] = fmaf(p, vv.y, o[d + 1]);
                o[d + 2] = fmaf(p, vv.z, o[d + 2]);
                o[d + 3] = fmaf(p, vv.w, o[d + 3]);
            }
        }
        mmax = mnew;
    }

    float inv = 1.f / lsum;
    float* optr = O + ((size_t)(b * Sv + qrow)) * Dv + h * DKv + hf * 32;
#pragma unroll
    for (int d = 0; d < 32; d += 4) {
        float4 t = make_float4(o[d] * inv, o[d + 1] * inv, o[d + 2] * inv, o[d + 3] * inv);
        *(float4*)(optr + d) = t;
    }
}

// ---------------- launch ------------------------------------------------------
extern "C" void kernel_launch(void* const* d_in, const int* in_sizes, int n_in,
                              void* d_out, int out_size) {
    const float* q  = (const float*)d_in[0];
    const float* k  = (const float*)d_in[1];
    const float* v  = (const float*)d_in[2];
    // d_in[3] = mask (tril) — handled analytically
    const float* Wq = (const float*)d_in[4];
    const float* Wk = (const float*)d_in[5];
    const float* Wv = (const float*)d_in[6];
    const float* Wo = (const float*)d_in[7];
    float* out = (float*)d_out;

    float *gq, *gk, *gv, *gc;
    cudaGetSymbolAddress((void**)&gq, g_Q);
    cudaGetSymbolAddress((void**)&gk, g_K);
    cudaGetSymbolAddress((void**)&gv, g_V);
    cudaGetSymbolAddress((void**)&gc, g_Ctx);

    cudaFuncSetAttribute(gemm_tc, cudaFuncAttributeMaxDynamicSharedMemorySize, GEMM_SMEM);

    dim3 gblock(256);
    dim3 ggrid(Dv / 128, MSZ / 128);   // (8, 32)

    gemm_tc<<<ggrid, gblock, GEMM_SMEM>>>(q, Wq, gq);
    gemm_tc<<<ggrid, gblock, GEMM_SMEM>>>(k, Wk, gk);
    gemm_tc<<<ggrid, gblock, GEMM_SMEM>>>(v, Wv, gv);

    dim3 ablock(256);
    dim3 agrid(Sv / AMQ, Bv * Hv);     // (16, 32)
    flash_attn2<<<agrid, ablock>>>(gq, gk, gv, gc);

    gemm_tc<<<ggrid, gblock, GEMM_SMEM>>>(gc, Wo, out);
}

// round 5
// speedup vs baseline: 2.7148x; 2.3868x over previous
#include <cuda_runtime.h>
#include <cuda_bf16.h>
#include <math.h>
#include <stdint.h>

#define Bv 2
#define Sv 2048
#define Dv 1024
#define Hv 16
#define DKv 64
#define MSZ (Bv * Sv)

// ---------------- scratch ---------------------------------------------------
__device__ float g_Q[MSZ * Dv];
__device__ float g_K[MSZ * Dv];
__device__ float g_V[MSZ * Dv];
// bf16 hi/lo splits of GEMM operands
__device__ __nv_bfloat16 g_qh[MSZ * Dv], g_ql[MSZ * Dv];
__device__ __nv_bfloat16 g_kh[MSZ * Dv], g_kl[MSZ * Dv];
__device__ __nv_bfloat16 g_vh[MSZ * Dv], g_vl[MSZ * Dv];
__device__ __nv_bfloat16 g_wqh[Dv * Dv], g_wql[Dv * Dv];
__device__ __nv_bfloat16 g_wkh[Dv * Dv], g_wkl[Dv * Dv];
__device__ __nv_bfloat16 g_wvh[Dv * Dv], g_wvl[Dv * Dv];
__device__ __nv_bfloat16 g_woh[Dv * Dv], g_wol[Dv * Dv];
__device__ __nv_bfloat16 g_ch[MSZ * Dv], g_cl[MSZ * Dv];

// ---------------- helpers ----------------------------------------------------
__device__ __forceinline__ uint32_t smem_u32(const void* p) {
    uint32_t a;
    asm("{ .reg .u64 t; cvta.to.shared.u64 t, %1; cvt.u32.u64 %0, t; }" : "=r"(a) : "l"(p));
    return a;
}
__device__ __forceinline__ void split4(float4 v, uint2& h, uint2& l) {
    __nv_bfloat162 h01 = __float22bfloat162_rn(make_float2(v.x, v.y));
    __nv_bfloat162 h23 = __float22bfloat162_rn(make_float2(v.z, v.w));
    float2 f01 = __bfloat1622float2(h01);
    float2 f23 = __bfloat1622float2(h23);
    __nv_bfloat162 l01 = __float22bfloat162_rn(make_float2(v.x - f01.x, v.y - f01.y));
    __nv_bfloat162 l23 = __float22bfloat162_rn(make_float2(v.z - f23.x, v.w - f23.y));
    h.x = *(uint32_t*)&h01; h.y = *(uint32_t*)&h23;
    l.x = *(uint32_t*)&l01; l.y = *(uint32_t*)&l23;
}
__device__ __forceinline__ void split2(float a, float b, uint32_t& h, uint32_t& l) {
    __nv_bfloat162 hb = __float22bfloat162_rn(make_float2(a, b));
    float2 hf = __bfloat1622float2(hb);
    __nv_bfloat162 lb = __float22bfloat162_rn(make_float2(a - hf.x, b - hf.y));
    h = *(uint32_t*)&hb; l = *(uint32_t*)&lb;
}
__device__ __forceinline__ uint32_t cvt2bf(float a, float b) {
    __nv_bfloat162 t = __float22bfloat162_rn(make_float2(a, b));
    return *(uint32_t*)&t;
}
__device__ __forceinline__ void mma_bf16(float* d, const uint32_t* a, const uint32_t* b) {
    asm volatile(
        "mma.sync.aligned.m16n8k16.row.col.f32.bf16.bf16.f32 "
        "{%0,%1,%2,%3}, {%4,%5,%6,%7}, {%8,%9}, {%0,%1,%2,%3};"
        : "+f"(d[0]), "+f"(d[1]), "+f"(d[2]), "+f"(d[3])
        : "r"(a[0]), "r"(a[1]), "r"(a[2]), "r"(a[3]), "r"(b[0]), "r"(b[1]));
}
__device__ __forceinline__ void ldsm_x2_t(uint32_t& r0, uint32_t& r1, uint32_t addr) {
    asm volatile("ldmatrix.sync.aligned.m8n8.x2.trans.shared.b16 {%0,%1}, [%2];"
                 : "=r"(r0), "=r"(r1) : "r"(addr));
}
__device__ __forceinline__ void cp16(uint32_t s, const void* g) {
    asm volatile("cp.async.cg.shared.global [%0], [%1], 16;" :: "r"(s), "l"(g));
}
#define CP_COMMIT() asm volatile("cp.async.commit_group;" ::: "memory")
#define CP_WAIT2()  asm volatile("cp.async.wait_group 2;" ::: "memory")

// ---------------- split kernel ------------------------------------------------
__global__ void split_kernel(const float4* __restrict__ src, uint2* __restrict__ hi,
                             uint2* __restrict__ lo, int n4) {
    int i = blockIdx.x * blockDim.x + threadIdx.x;
    if (i < n4) {
        uint2 h, l;
        split4(src[i], h, l);
        hi[i] = h; lo[i] = l;
    }
}

// ---------------- GEMM: C = A * B^T, bf16 hi/lo inputs -------------------------
// CTA 128x128, 8 warps (2m x 4n), KC=32, 4-stage cp.async pipeline, 3x split MMA.
#define KC 32
#define NCH (Dv / KC)           // 32
#define ROWB 80                 // 64B data + 16B pad (validated conflict-free)
#define TILEB (128 * ROWB)      // 10240
#define STAGEB (4 * TILEB)      // 40960: Ah, Al, Bh, Bl
#define GEMM_SMEM (4 * STAGEB)  // 163840

__global__ __launch_bounds__(256, 1)
void gemm_tc(const __nv_bfloat16* __restrict__ Ah, const __nv_bfloat16* __restrict__ Al,
             const __nv_bfloat16* __restrict__ Bh, const __nv_bfloat16* __restrict__ Bl,
             float* __restrict__ C) {
    extern __shared__ char smem[];
    const uint32_t sbase = smem_u32(smem);
    const int tid = threadIdx.x;
    const int wid = tid >> 5;
    const int lid = tid & 31;
    const int g = lid >> 2;
    const int tig = lid & 3;
    const int warp_m = wid & 1;
    const int warp_n = wid >> 1;
    const int row0 = blockIdx.y * 128;
    const int col0 = blockIdx.x * 128;

    const __nv_bfloat16* srcs[4] = {Ah, Al, Bh, Bl};
    const int mytile = wid >> 1;
    const int myhalf = wid & 1;
    const __nv_bfloat16* mysrc = srcs[mytile];
    const int myrbase = (mytile < 2) ? row0 : col0;

    float acc[4][4][4];
#pragma unroll
    for (int i = 0; i < 4; ++i)
#pragma unroll
        for (int j = 0; j < 4; ++j)
#pragma unroll
            for (int e = 0; e < 4; ++e) acc[i][j][e] = 0.f;

    auto issue = [&](int chunk, int st) {
        const int k0 = chunk * KC;
#pragma unroll
        for (int rr = 0; rr < 2; ++rr) {
            int r = myhalf * 64 + rr * 32 + lid;
            const char* gp = (const char*)(mysrc + (size_t)(myrbase + r) * Dv + k0);
            uint32_t sa = sbase + st * STAGEB + mytile * TILEB + r * ROWB;
#pragma unroll
            for (int q = 0; q < 4; ++q) cp16(sa + q * 16, gp + q * 16);
        }
    };

    auto compute = [&](int s) {
        const char* st = smem + s * STAGEB;
#pragma unroll
        for (int ks = 0; ks < 2; ++ks) {
            const int kb = ks * 32;
            uint32_t ah[4][4], al[4][4], bh[4][2], bl[4][2];
#pragma unroll
            for (int mt = 0; mt < 4; ++mt) {
                int r = warp_m * 64 + mt * 16 + g;
                const char* p = st + r * ROWB + tig * 4 + kb;
                ah[mt][0] = *(const uint32_t*)(p);
                ah[mt][1] = *(const uint32_t*)(p + 8 * ROWB);
                ah[mt][2] = *(const uint32_t*)(p + 16);
                ah[mt][3] = *(const uint32_t*)(p + 8 * ROWB + 16);
                al[mt][0] = *(const uint32_t*)(p + TILEB);
                al[mt][1] = *(const uint32_t*)(p + TILEB + 8 * ROWB);
                al[mt][2] = *(const uint32_t*)(p + TILEB + 16);
                al[mt][3] = *(const uint32_t*)(p + TILEB + 8 * ROWB + 16);
            }
#pragma unroll
            for (int nt = 0; nt < 4; ++nt) {
                int r = warp_n * 32 + nt * 8 + g;
                const char* p = st + 2 * TILEB + r * ROWB + tig * 4 + kb;
                bh[nt][0] = *(const uint32_t*)(p);
                bh[nt][1] = *(const uint32_t*)(p + 16);
                bl[nt][0] = *(const uint32_t*)(p + TILEB);
                bl[nt][1] = *(const uint32_t*)(p + TILEB + 16);
            }
#pragma unroll
            for (int mt = 0; mt < 4; ++mt)
#pragma unroll
                for (int nt = 0; nt < 4; ++nt) {
                    mma_bf16(acc[mt][nt], ah[mt], bh[nt]);
                    mma_bf16(acc[mt][nt], ah[mt], bl[nt]);
                    mma_bf16(acc[mt][nt], al[mt], bh[nt]);
                }
        }
    };

#pragma unroll
    for (int p = 0; p < 3; ++p) {
        issue(p, p);
        CP_COMMIT();
    }
    for (int i = 0; i < NCH; ++i) {
        CP_WAIT2();
        __syncthreads();
        if (i + 3 < NCH) issue(i + 3, (i + 3) & 3);
        CP_COMMIT();
        compute(i & 3);
    }

#pragma unroll
    for (int mt = 0; mt < 4; ++mt)
#pragma unroll
        for (int nt = 0; nt < 4; ++nt) {
            int r = row0 + warp_m * 64 + mt * 16 + g;
            int c = col0 + warp_n * 32 + nt * 8 + 2 * tig;
            float* d = acc[mt][nt];
            *(float2*)&C[(size_t)r * Dv + c] = make_float2(d[0], d[1]);
            *(float2*)&C[(size_t)(r + 8) * Dv + c] = make_float2(d[2], d[3]);
        }
}

// ---------------- tensor-core flash attention ---------------------------------
// CTA: 64 queries of one (b,h); 4 warps x 16 rows. K tiles of 64.
// QK^T and P.V both use 3x bf16 hi/lo split -> fp32-grade accuracy.
#define FP 144                    // padded row bytes for 64 bf16
#define FT (64 * FP)              // 9216 per tile
#define FLASH_SMEM (6 * FT)       // Qh Ql Kh Kl Vh Vl = 55296

__global__ __launch_bounds__(128)
void flash_mma(const float* __restrict__ Q, const float* __restrict__ K,
               const float* __restrict__ V,
               __nv_bfloat16* __restrict__ Ch, __nv_bfloat16* __restrict__ Cl) {
    extern __shared__ char fsm[];
    char* sQh = fsm;
    char* sQl = fsm + FT;
    char* sKh = fsm + 2 * FT;
    char* sKl = fsm + 3 * FT;
    char* sVh = fsm + 4 * FT;
    char* sVl = fsm + 5 * FT;

    const int bh = blockIdx.y;
    const int b = bh >> 4;
    const int h = bh & 15;
    const int qt = blockIdx.x;
    const int q0 = qt * 64;
    const int tid = threadIdx.x;
    const int w = tid >> 5;
    const int lane = tid & 31;
    const int g = lane >> 2;
    const int tig = lane & 3;
    const uint32_t sVh_u = smem_u32(sVh);
    const uint32_t sVl_u = smem_u32(sVl);

    // stage Q (pre-scaled by 1/sqrt(dk)=0.125), split hi/lo
#pragma unroll
    for (int j = 0; j < 8; ++j) {
        int idx = tid + j * 128;
        int r = idx >> 4;
        int c = (idx & 15) * 4;
        float4 t = *(const float4*)&Q[(size_t)(b * Sv + q0 + r) * Dv + h * DKv + c];
        t.x *= 0.125f; t.y *= 0.125f; t.z *= 0.125f; t.w *= 0.125f;
        uint2 hh, ll;
        split4(t, hh, ll);
        *(uint2*)(sQh + r * FP + c * 2) = hh;
        *(uint2*)(sQl + r * FP + c * 2) = ll;
    }

    float oacc[8][4];
#pragma unroll
    for (int nt = 0; nt < 8; ++nt)
#pragma unroll
        for (int e = 0; e < 4; ++e) oacc[nt][e] = 0.f;
    float m0 = -1e30f, m1 = -1e30f, l0 = 0.f, l1 = 0.f;

    for (int kt = 0; kt <= qt; ++kt) {
        __syncthreads();
        const int k0 = kt * 64;
#pragma unroll
        for (int j = 0; j < 8; ++j) {
            int idx = tid + j * 128;
            int r = idx >> 4;
            int c = (idx & 15) * 4;
            size_t base = (size_t)(b * Sv + k0 + r) * Dv + h * DKv + c;
            float4 t = *(const float4*)&K[base];
            uint2 hh, ll;
            split4(t, hh, ll);
            *(uint2*)(sKh + r * FP + c * 2) = hh;
            *(uint2*)(sKl + r * FP + c * 2) = ll;
            float4 u = *(const float4*)&V[base];
            split4(u, hh, ll);
            *(uint2*)(sVh + r * FP + c * 2) = hh;
            *(uint2*)(sVl + r * FP + c * 2) = ll;
        }
        __syncthreads();

        // ---- S = Q K^T (3x split) ----
        float s[8][4];
#pragma unroll
        for (int nt = 0; nt < 8; ++nt)
#pragma unroll
            for (int e = 0; e < 4; ++e) s[nt][e] = 0.f;
#pragma unroll
        for (int ks = 0; ks < 4; ++ks) {
            const int kb = ks * 32;
            uint32_t ah[4], al[4];
            const char* pq = sQh + (w * 16 + g) * FP + tig * 4 + kb;
            ah[0] = *(const uint32_t*)(pq);
            ah[1] = *(const uint32_t*)(pq + 8 * FP);
            ah[2] = *(const uint32_t*)(pq + 16);
            ah[3] = *(const uint32_t*)(pq + 8 * FP + 16);
            const char* pl = sQl + (w * 16 + g) * FP + tig * 4 + kb;
            al[0] = *(const uint32_t*)(pl);
            al[1] = *(const uint32_t*)(pl + 8 * FP);
            al[2] = *(const uint32_t*)(pl + 16);
            al[3] = *(const uint32_t*)(pl + 8 * FP + 16);
#pragma unroll
            for (int nt = 0; nt < 8; ++nt) {
                uint32_t bh2[2], bl2[2];
                const char* pk = sKh + (nt * 8 + g) * FP + tig * 4 + kb;
                bh2[0] = *(const uint32_t*)(pk);
                bh2[1] = *(const uint32_t*)(pk + 16);
                const char* pk2 = sKl + (nt * 8 + g) * FP + tig * 4 + kb;
                bl2[0] = *(const uint32_t*)(pk2);
                bl2[1] = *(const uint32_t*)(pk2 + 16);
                mma_bf16(s[nt], ah, bh2);
                mma_bf16(s[nt], ah, bl2);
                mma_bf16(s[nt], al, bh2);
            }
        }

        // ---- causal mask on diagonal tile ----
        if (kt == qt) {
            const int rlo = w * 16 + g;
            const int rhi = rlo + 8;
#pragma unroll
            for (int nt = 0; nt < 8; ++nt) {
                int c0 = nt * 8 + 2 * tig;
                if (c0 > rlo) s[nt][0] = -1e30f;
                if (c0 + 1 > rlo) s[nt][1] = -1e30f;
                if (c0 > rhi) s[nt][2] = -1e30f;
                if (c0 + 1 > rhi) s[nt][3] = -1e30f;
            }
        }

        // ---- online softmax ----
        float mx0 = -1e30f, mx1 = -1e30f;
#pragma unroll
        for (int nt = 0; nt < 8; ++nt) {
            mx0 = fmaxf(mx0, fmaxf(s[nt][0], s[nt][1]));
            mx1 = fmaxf(mx1, fmaxf(s[nt][2], s[nt][3]));
        }
        mx0 = fmaxf(mx0, __shfl_xor_sync(0xffffffffu, mx0, 1));
        mx0 = fmaxf(mx0, __shfl_xor_sync(0xffffffffu, mx0, 2));
        mx1 = fmaxf(mx1, __shfl_xor_sync(0xffffffffu, mx1, 1));
        mx1 = fmaxf(mx1, __shfl_xor_sync(0xffffffffu, mx1, 2));
        float mn0 = fmaxf(m0, mx0), mn1 = fmaxf(m1, mx1);
        float a0 = __expf(m0 - mn0), a1 = __expf(m1 - mn1);
        m0 = mn0; m1 = mn1;

        float ps0 = 0.f, ps1 = 0.f;
#pragma unroll
        for (int nt = 0; nt < 8; ++nt) {
            s[nt][0] = __expf(s[nt][0] - m0);
            s[nt][1] = __expf(s[nt][1] - m0);
            s[nt][2] = __expf(s[nt][2] - m1);
            s[nt][3] = __expf(s[nt][3] - m1);
            ps0 += s[nt][0] + s[nt][1];
            ps1 += s[nt][2] + s[nt][3];
        }
        ps0 += __shfl_xor_sync(0xffffffffu, ps0, 1);
        ps0 += __shfl_xor_sync(0xffffffffu, ps0, 2);
        ps1 += __shfl_xor_sync(0xffffffffu, ps1, 1);
        ps1 += __shfl_xor_sync(0xffffffffu, ps1, 2);
        l0 = l0 * a0 + ps0;
        l1 = l1 * a1 + ps1;
#pragma unroll
        for (int nt = 0; nt < 8; ++nt) {
            oacc[nt][0] *= a0; oacc[nt][1] *= a0;
            oacc[nt][2] *= a1; oacc[nt][3] *= a1;
        }

        // ---- O += P V (3x split) ----
#pragma unroll
        for (int kc = 0; kc < 4; ++kc) {
            uint32_t pah[4], pal[4];
            split2(s[2 * kc][0], s[2 * kc][1], pah[0], pal[0]);
            split2(s[2 * kc][2], s[2 * kc][3], pah[1], pal[1]);
            split2(s[2 * kc + 1][0], s[2 * kc + 1][1], pah[2], pal[2]);
            split2(s[2 * kc + 1][2], s[2 * kc + 1][3], pah[3], pal[3]);
            uint32_t rowoff = (uint32_t)((kc * 16 + (lane & 15)) * FP);
#pragma unroll
            for (int nt = 0; nt < 8; ++nt) {
                uint32_t vh2[2], vl2[2];
                ldsm_x2_t(vh2[0], vh2[1], sVh_u + rowoff + nt * 16);
                ldsm_x2_t(vl2[0], vl2[1], sVl_u + rowoff + nt * 16);
                mma_bf16(oacc[nt], pah, vh2);
                mma_bf16(oacc[nt], pah, vl2);
                mma_bf16(oacc[nt], pal, vh2);
            }
        }
    }

    // ---- epilogue: normalize, split to bf16 hi/lo ctx ----
    float inv0 = 1.f / l0, inv1 = 1.f / l1;
    const size_t rlo = (size_t)(b * Sv + q0 + w * 16 + g);
    const size_t rhi = rlo + 8;
#pragma unroll
    for (int nt = 0; nt < 8; ++nt) {
        int c = h * DKv + nt * 8 + 2 * tig;
        float f0 = oacc[nt][0] * inv0, f1 = oacc[nt][1] * inv0;
        float f2 = oacc[nt][2] * inv1, f3 = oacc[nt][3] * inv1;
        uint32_t h01, l01, h23, l23;
        split2(f0, f1, h01, l01);
        split2(f2, f3, h23, l23);
        *(uint32_t*)&Ch[rlo * Dv + c] = h01;
        *(uint32_t*)&Cl[rlo * Dv + c] = l01;
        *(uint32_t*)&Ch[rhi * Dv + c] = h23;
        *(uint32_t*)&Cl[rhi * Dv + c] = l23;
    }
}

// ---------------- launch --------------------------------------------------------
extern "C" void kernel_launch(void* const* d_in, const int* in_sizes, int n_in,
                              void* d_out, int out_size) {
    const float* q  = (const float*)d_in[0];
    const float* k  = (const float*)d_in[1];
    const float* v  = (const float*)d_in[2];
    // d_in[3] = mask (tril) — handled analytically
    const float* Wq = (const float*)d_in[4];
    const float* Wk = (const float*)d_in[5];
    const float* Wv = (const float*)d_in[6];
    const float* Wo = (const float*)d_in[7];
    float* out = (float*)d_out;

    float *gq, *gk, *gv;
    cudaGetSymbolAddress((void**)&gq, g_Q);
    cudaGetSymbolAddress((void**)&gk, g_K);
    cudaGetSymbolAddress((void**)&gv, g_V);
    __nv_bfloat16 *qh, *ql, *kh, *kl, *vh, *vl;
    __nv_bfloat16 *wqh, *wql, *wkh, *wkl, *wvh, *wvl, *woh, *wol, *ch, *cl;
    cudaGetSymbolAddress((void**)&qh, g_qh);  cudaGetSymbolAddress((void**)&ql, g_ql);
    cudaGetSymbolAddress((void**)&kh, g_kh);  cudaGetSymbolAddress((void**)&kl, g_kl);
    cudaGetSymbolAddress((void**)&vh, g_vh);  cudaGetSymbolAddress((void**)&vl, g_vl);
    cudaGetSymbolAddress((void**)&wqh, g_wqh); cudaGetSymbolAddress((void**)&wql, g_wql);
    cudaGetSymbolAddress((void**)&wkh, g_wkh); cudaGetSymbolAddress((void**)&wkl, g_wkl);
    cudaGetSymbolAddress((void**)&wvh, g_wvh); cudaGetSymbolAddress((void**)&wvl, g_wvl);
    cudaGetSymbolAddress((void**)&woh, g_woh); cudaGetSymbolAddress((void**)&wol, g_wol);
    cudaGetSymbolAddress((void**)&ch, g_ch);   cudaGetSymbolAddress((void**)&cl, g_cl);

    const int nQK4 = MSZ * Dv / 4;
    const int nW4  = Dv * Dv / 4;
    split_kernel<<<nQK4 / 256, 256>>>((const float4*)q, (uint2*)qh, (uint2*)ql, nQK4);
    split_kernel<<<nQK4 / 256, 256>>>((const float4*)k, (uint2*)kh, (uint2*)kl, nQK4);
    split_kernel<<<nQK4 / 256, 256>>>((const float4*)v, (uint2*)vh, (uint2*)vl, nQK4);
    split_kernel<<<nW4 / 256, 256>>>((const float4*)Wq, (uint2*)wqh, (uint2*)wql, nW4);
    split_kernel<<<nW4 / 256, 256>>>((const float4*)Wk, (uint2*)wkh, (uint2*)wkl, nW4);
    split_kernel<<<nW4 / 256, 256>>>((const float4*)Wv, (uint2*)wvh, (uint2*)wvl, nW4);
    split_kernel<<<nW4 / 256, 256>>>((const float4*)Wo, (uint2*)woh, (uint2*)wol, nW4);

    cudaFuncSetAttribute(gemm_tc, cudaFuncAttributeMaxDynamicSharedMemorySize, GEMM_SMEM);
    cudaFuncSetAttribute(flash_mma, cudaFuncAttributeMaxDynamicSharedMemorySize, FLASH_SMEM);

    dim3 gblock(256);
    dim3 ggrid(Dv / 128, MSZ / 128);   // (8, 32)
    gemm_tc<<<ggrid, gblock, GEMM_SMEM>>>(qh, ql, wqh, wql, gq);
    gemm_tc<<<ggrid, gblock, GEMM_SMEM>>>(kh, kl, wkh, wkl, gk);
    gemm_tc<<<ggrid, gblock, GEMM_SMEM>>>(vh, vl, wvh, wvl, gv);

    dim3 agrid(Sv / 64, Bv * Hv);      // (32, 32)
    flash_mma<<<agrid, 128, FLASH_SMEM>>>(gq, gk, gv, ch, cl);

    gemm_tc<<<ggrid, gblock, GEMM_SMEM>>>(ch, cl, woh, wol, out);
}